// round 10
// baseline (speedup 1.0000x reference)
#include <cuda_runtime.h>
#include <cuda_bf16.h>
#include <cstddef>
#include <cstdint>

#define NROWS 32768
#define EDIM  1024
#define MSIZE 2048
typedef __nv_bfloat16 bf16;

// ---------------- scratch ----------------------------------------------------
__device__ float g_part[4096];
__device__ float g_scal[8];           // 0 xmax, 1 hmax, 2 wsk, 3 wso
__device__ bf16  g_qxb [(size_t)NROWS * EDIM];    // qx / qh as exact-int bf16
__device__ bf16  g_qwkT[(size_t)EDIM * EDIM];     // quantized Wk, transposed [i,d]
__device__ bf16  g_qwob[(size_t)EDIM * EDIM];     // quantized Wo [o,i]
__device__ bf16  g_mkhi[(size_t)MSIZE * EDIM];
__device__ bf16  g_mklo[(size_t)MSIZE * EDIM];
__device__ bf16  g_ghi [(size_t)MSIZE * EDIM];
__device__ bf16  g_glo [(size_t)MSIZE * EDIM];
__device__ bf16  g_mhiT[(size_t)EDIM * MSIZE];
__device__ bf16  g_mloT[(size_t)EDIM * MSIZE];
__device__ float g_c   [MSIZE];
__device__ float g_sim [(size_t)NROWS * MSIZE];
__device__ bf16  g_ahi [(size_t)NROWS * MSIZE];
__device__ bf16  g_alo [(size_t)NROWS * MSIZE];
__device__ float g_h   [(size_t)NROWS * EDIM];

// ---------------- helpers ----------------------------------------------------
__device__ __forceinline__ uint32_t smem_u32(const void* p) {
    uint32_t a;
    asm("{ .reg .u64 t; cvta.to.shared.u64 t, %1; cvt.u32.u64 %0, t; }" : "=r"(a) : "l"(p));
    return a;
}
// 128B-row swizzle: 16B unit g ^= (row & 7)
__device__ __forceinline__ uint32_t sw_addr(uint32_t base, int r, int g) {
    return base + r * 128 + ((g ^ (r & 7)) << 4);
}
__device__ __forceinline__ void cp16(uint32_t s, const void* g) {
    asm volatile("cp.async.cg.shared.global [%0], [%1], 16;" :: "r"(s), "l"(g));
}
#define CP_COMMIT() asm volatile("cp.async.commit_group;" ::: "memory")
#define CP_WAIT0()  asm volatile("cp.async.wait_group 0;" ::: "memory")
#define LDSM4(r0, r1, r2, r3, addr) \
    asm volatile("ldmatrix.sync.aligned.m8n8.x4.shared.b16 {%0,%1,%2,%3}, [%4];" \
                 : "=r"(r0), "=r"(r1), "=r"(r2), "=r"(r3) : "r"(addr))
#define MMA_BF16(c, a, b0r, b1r) \
    asm volatile("mma.sync.aligned.m16n8k16.row.col.f32.bf16.bf16.f32 " \
                 "{%0,%1,%2,%3}, {%4,%5,%6,%7}, {%8,%9}, {%0,%1,%2,%3};" \
                 : "+f"((c)[0]), "+f"((c)[1]), "+f"((c)[2]), "+f"((c)[3]) \
                 : "r"((a)[0]), "r"((a)[1]), "r"((a)[2]), "r"((a)[3]), "r"(b0r), "r"(b1r))

// ---------------- reductions -------------------------------------------------
__global__ void absmax_part(const float* __restrict__ x, size_t n4, float* __restrict__ part) {
    const float4* x4 = (const float4*)x;
    float m = 0.f;
    for (size_t i = (size_t)blockIdx.x * blockDim.x + threadIdx.x; i < n4;
         i += (size_t)gridDim.x * blockDim.x) {
        float4 v = x4[i];
        m = fmaxf(m, fmaxf(fmaxf(fabsf(v.x), fabsf(v.y)), fmaxf(fabsf(v.z), fabsf(v.w))));
    }
    __shared__ float red[256];
    red[threadIdx.x] = m; __syncthreads();
    for (int s = 128; s > 0; s >>= 1) {
        if (threadIdx.x < s) red[threadIdx.x] = fmaxf(red[threadIdx.x], red[threadIdx.x + s]);
        __syncthreads();
    }
    if (threadIdx.x == 0) part[blockIdx.x] = red[0];
}

__global__ void abssum_part(const float* __restrict__ x, size_t n4, float* __restrict__ part) {
    const float4* x4 = (const float4*)x;
    float s = 0.f;
    for (size_t i = (size_t)blockIdx.x * blockDim.x + threadIdx.x; i < n4;
         i += (size_t)gridDim.x * blockDim.x) {
        float4 v = x4[i];
        s += fabsf(v.x) + fabsf(v.y) + fabsf(v.z) + fabsf(v.w);
    }
    __shared__ float red[256];
    red[threadIdx.x] = s; __syncthreads();
    for (int st = 128; st > 0; st >>= 1) {
        if (threadIdx.x < st) red[threadIdx.x] += red[threadIdx.x + st];
        __syncthreads();
    }
    if (threadIdx.x == 0) part[blockIdx.x] = red[0];
}

__global__ void finalize_max(const float* __restrict__ part, int npart, float* __restrict__ out) {
    __shared__ float red[256];
    float m = 0.f;
    for (int i = threadIdx.x; i < npart; i += 256) m = fmaxf(m, part[i]);
    red[threadIdx.x] = m; __syncthreads();
    for (int s = 128; s > 0; s >>= 1) {
        if (threadIdx.x < s) red[threadIdx.x] = fmaxf(red[threadIdx.x], red[threadIdx.x + s]);
        __syncthreads();
    }
    if (threadIdx.x == 0) out[0] = red[0];
}

__global__ void finalize_mean(const float* __restrict__ part, int npart, float* __restrict__ out, float n) {
    __shared__ float red[256];
    float s = 0.f;
    for (int i = threadIdx.x; i < npart; i += 256) s += part[i];
    red[threadIdx.x] = s; __syncthreads();
    for (int st = 128; st > 0; st >>= 1) {
        if (threadIdx.x < st) red[threadIdx.x] += red[threadIdx.x + st];
        __syncthreads();
    }
    if (threadIdx.x == 0) out[0] = __fdiv_rn(red[0], n);
}

// ---------------- quantize / split / transpose -------------------------------
__global__ void quantize_act_bf16(const float* __restrict__ x, bf16* __restrict__ q,
                                  const float* __restrict__ amax, size_t n4) {
    size_t i = (size_t)blockIdx.x * blockDim.x + threadIdx.x;
    if (i >= n4) return;
    float iscale = __fdiv_rn(amax[0], 127.0f);
    float4 v = ((const float4*)x)[i];
    float r0 = fminf(fmaxf(rintf(__fdiv_rn(v.x, iscale)), -128.f), 127.f);
    float r1 = fminf(fmaxf(rintf(__fdiv_rn(v.y, iscale)), -128.f), 127.f);
    float r2 = fminf(fmaxf(rintf(__fdiv_rn(v.z, iscale)), -128.f), 127.f);
    float r3 = fminf(fmaxf(rintf(__fdiv_rn(v.w, iscale)), -128.f), 127.f);
    bf16* o = q + i * 4;
    o[0] = __float2bfloat16(r0); o[1] = __float2bfloat16(r1);
    o[2] = __float2bfloat16(r2); o[3] = __float2bfloat16(r3);
}

__global__ void quantize_w_bf16(const float* __restrict__ W, bf16* __restrict__ q,
                                const float* __restrict__ wscale, size_t n) {
    size_t i = (size_t)blockIdx.x * blockDim.x + threadIdx.x;
    if (i >= n) return;
    float thr = 0.5f * wscale[0];
    float v = W[i];
    float o = (fabsf(v) > thr) ? (v > 0.f ? 1.f : -1.f) : 0.f;
    q[i] = __float2bfloat16(o);
}

// quantize Wk to bf16 ternary, transposed: q[i,d] = quant(W[d,i])
__global__ void tq_wkT(const float* __restrict__ W, bf16* __restrict__ q,
                       const float* __restrict__ scal) {
    __shared__ float t[32][33];
    int bd = blockIdx.y * 32, bi = blockIdx.x * 32;
    for (int j = threadIdx.y; j < 32; j += 8)
        t[j][threadIdx.x] = W[(size_t)(bd + j) * EDIM + bi + threadIdx.x];
    __syncthreads();
    float thr = 0.5f * scal[2];
    for (int j = threadIdx.y; j < 32; j += 8) {
        float v = t[threadIdx.x][j];
        float o = (fabsf(v) > thr) ? (v > 0.f ? 1.f : -1.f) : 0.f;
        q[(size_t)(bi + j) * EDIM + bd + threadIdx.x] = __float2bfloat16(o);
    }
}

// fp32 -> (hi, lo) bf16 split
__global__ void split2(const float* __restrict__ X, bf16* __restrict__ hi,
                       bf16* __restrict__ lo, size_t n) {
    size_t i = (size_t)blockIdx.x * blockDim.x + threadIdx.x;
    if (i >= n) return;
    float v = X[i];
    bf16 h = __float2bfloat16(v);
    hi[i] = h;
    lo[i] = __float2bfloat16(v - __bfloat162float(h));
}

// mv [MSIZE, EDIM] -> transposed split [EDIM, MSIZE]
__global__ void transpose_split(const float* __restrict__ mv, bf16* __restrict__ hi,
                                bf16* __restrict__ lo) {
    __shared__ float t[32][33];
    int bx = blockIdx.x * 32, by = blockIdx.y * 32;   // bx: e, by: m
    for (int i = threadIdx.y; i < 32; i += 8)
        t[i][threadIdx.x] = mv[(size_t)(by + i) * EDIM + bx + threadIdx.x];
    __syncthreads();
    for (int i = threadIdx.y; i < 32; i += 8) {
        float v = t[threadIdx.x][i];
        bf16 h = __float2bfloat16(v);
        size_t o = (size_t)(bx + i) * MSIZE + by + threadIdx.x;
        hi[o] = h;
        lo[o] = __float2bfloat16(v - __bfloat162float(h));
    }
}

__global__ void cvec_k(const float* __restrict__ mk, const float* __restrict__ bk,
                       float* __restrict__ c) {
    int m = blockIdx.x * 8 + (threadIdx.x >> 5);
    int lane = threadIdx.x & 31;
    const float4* row = (const float4*)(mk + (size_t)m * EDIM);
    const float4* b4 = (const float4*)bk;
    float s = 0.f;
    for (int i = lane; i < EDIM / 4; i += 32) {
        float4 a = row[i], b = b4[i];
        s += a.x * b.x + a.y * b.y + a.z * b.z + a.w * b.w;
    }
    for (int o = 16; o > 0; o >>= 1) s += __shfl_xor_sync(0xffffffffu, s, o);
    if (lane == 0) c[m] = s;
}

// -------- row softmax (+ c[m]/32), emit 2-level bf16 attn --------------------
__global__ void softmax_split(const float* __restrict__ S, const float* __restrict__ c,
                              bf16* __restrict__ ahi, bf16* __restrict__ alo) {
    const size_t row = blockIdx.x;
    const float* p = S + row * (size_t)MSIZE;
    const int tid = threadIdx.x;
    float v[8];
#pragma unroll
    for (int i = 0; i < 8; i++) v[i] = p[tid + i * 256] + c[tid + i * 256] * 0.03125f;
    float m = v[0];
#pragma unroll
    for (int i = 1; i < 8; i++) m = fmaxf(m, v[i]);
    __shared__ float red[256];
    red[tid] = m; __syncthreads();
    for (int s = 128; s > 0; s >>= 1) {
        if (tid < s) red[tid] = fmaxf(red[tid], red[tid + s]);
        __syncthreads();
    }
    const float rowmax = red[0];
    __syncthreads();
    float sum = 0.f;
#pragma unroll
    for (int i = 0; i < 8; i++) { v[i] = expf(v[i] - rowmax); sum += v[i]; }
    red[tid] = sum; __syncthreads();
    for (int s = 128; s > 0; s >>= 1) {
        if (tid < s) red[tid] += red[tid + s];
        __syncthreads();
    }
    const float inv = __fdiv_rn(1.0f, red[0]);
#pragma unroll
    for (int i = 0; i < 8; i++) {
        float a = v[i] * inv;
        bf16 h = __float2bfloat16(a);
        size_t o = row * (size_t)MSIZE + tid + i * 256;
        ahi[o] = h;
        alo[o] = __float2bfloat16(a - __bfloat162float(h));
    }
}

// ======= bf16 mma.sync GEMM NT, 128x256 tile, 512 thr, multi-pass accum ======
// D[128,256] = sum_p A_p[bm.., K] @ B_p[bn.., K]^T    (fp32 accum)
// mode 0: C = D*alpha0   (alpha0 = 0.03125*wsk*xmax/127)
// mode 1: C = D + aux (residual), block absmax -> part
// mode 2: C = D*alpha2 + aux[col]
// mode 3: (Ohi,Olo) = bf16 split of D
__device__ __forceinline__ void load_chunk(const bf16* A, const bf16* B, int K,
                                           int bm, int bn, int kc,
                                           uint32_t sA, uint32_t sB, int tid) {
    int r = tid >> 3, g = tid & 7;       // r: 0..63
    const bf16* ga = A + (size_t)(bm + r) * K + kc * 64 + g * 8;
    const bf16* gb = B + (size_t)(bn + r) * K + kc * 64 + g * 8;
#pragma unroll
    for (int i = 0; i < 2; i++)
        cp16(sw_addr(sA, r + i * 64, g), ga + (size_t)i * 64 * K);
#pragma unroll
    for (int i = 0; i < 4; i++)
        cp16(sw_addr(sB, r + i * 64, g), gb + (size_t)i * 64 * K);
}

__global__ __launch_bounds__(512)
void tc_gemm(const bf16* A0, const bf16* A1, const bf16* A2,
             const bf16* B0, const bf16* B1, const bf16* B2,
             int npass, int K, float* __restrict__ C, const float* __restrict__ aux,
             const float* __restrict__ scal, float* __restrict__ part, int mode, int M,
             bf16* __restrict__ Ohi, bf16* __restrict__ Olo) {
    extern __shared__ char dsm[];
    __shared__ float red[512];
    const int tid = threadIdx.x, l = tid & 31, w = tid >> 5;
    const int bm = blockIdx.y * 128, bn = blockIdx.x * 256;
    const int wm = (w & 3) * 32, wn = (w >> 2) * 64;
    const int kchunks = K >> 6, total = npass * kchunks;
    const bf16* Ap[3] = {A0, A1, A2};
    const bf16* Bp[3] = {B0, B1, B2};
    const uint32_t sbase = smem_u32(dsm);

    float acc[2][8][4];
#pragma unroll
    for (int i = 0; i < 2; i++)
#pragma unroll
        for (int j = 0; j < 8; j++)
#pragma unroll
            for (int k = 0; k < 4; k++) acc[i][j][k] = 0.f;

    load_chunk(Ap[0], Bp[0], K, bm, bn, 0, sbase, sbase + 16384, tid);
    CP_COMMIT();
    CP_WAIT0();
    __syncthreads();

    for (int ch = 0; ch < total; ch++) {
        const int s = ch & 1;
        const uint32_t sA = sbase + s * 49152, sB = sA + 16384;
        if (ch + 1 < total) {
            int p = (ch + 1) / kchunks, kc = (ch + 1) % kchunks;
            uint32_t nA = sbase + (s ^ 1) * 49152;
            load_chunk(Ap[p], Bp[p], K, bm, bn, kc, nA, nA + 16384, tid);
            CP_COMMIT();
        }
        const int rA = wm + (l & 15);
        const int rB = wn + (l & 7) + ((l & 16) ? 8 : 0);
#pragma unroll
        for (int ks = 0; ks < 4; ks++) {
            uint32_t a[2][4], b[4][4];
            const int gA = ks * 2 + (l >> 4);
            const int gB = ks * 2 + ((l >> 3) & 1);
#pragma unroll
            for (int mt = 0; mt < 2; mt++)
                LDSM4(a[mt][0], a[mt][1], a[mt][2], a[mt][3], sw_addr(sA, rA + mt * 16, gA));
#pragma unroll
            for (int tp = 0; tp < 4; tp++)
                LDSM4(b[tp][0], b[tp][1], b[tp][2], b[tp][3], sw_addr(sB, rB + tp * 16, gB));
#pragma unroll
            for (int mt = 0; mt < 2; mt++)
#pragma unroll
                for (int nt = 0; nt < 8; nt++)
                    MMA_BF16(acc[mt][nt], a[mt], b[nt >> 1][(nt & 1) * 2], b[nt >> 1][(nt & 1) * 2 + 1]);
        }
        if (ch + 1 < total) CP_WAIT0();
        __syncthreads();
    }

    float alpha = 1.f;
    if (mode == 0) alpha = 0.03125f * scal[2] * __fdiv_rn(scal[0], 127.0f);
    else if (mode == 2) alpha = scal[3] * __fdiv_rn(scal[1], 127.0f);
    float lmax = 0.f;
    const int rr = bm + wm + (l >> 2);
    const int cb = bn + wn + (l & 3) * 2;
#pragma unroll
    for (int mt = 0; mt < 2; mt++) {
        int r0 = rr + mt * 16;
#pragma unroll
        for (int nt = 0; nt < 8; nt++) {
            int cc = cb + nt * 8;
            float v0 = acc[mt][nt][0], v1 = acc[mt][nt][1];
            float v2 = acc[mt][nt][2], v3 = acc[mt][nt][3];
            if (mode == 3) {
                bf16 h0 = __float2bfloat16(v0), h1 = __float2bfloat16(v1);
                bf16 h2 = __float2bfloat16(v2), h3 = __float2bfloat16(v3);
                size_t o0 = (size_t)r0 * M + cc, o1 = (size_t)(r0 + 8) * M + cc;
                Ohi[o0] = h0; Ohi[o0 + 1] = h1; Ohi[o1] = h2; Ohi[o1 + 1] = h3;
                Olo[o0] = __float2bfloat16(v0 - __bfloat162float(h0));
                Olo[o0 + 1] = __float2bfloat16(v1 - __bfloat162float(h1));
                Olo[o1] = __float2bfloat16(v2 - __bfloat162float(h2));
                Olo[o1 + 1] = __float2bfloat16(v3 - __bfloat162float(h3));
                continue;
            }
            float* p0 = C + (size_t)r0 * M + cc;
            float* p1 = p0 + (size_t)8 * M;
            if (mode == 1) {
                const float* x0 = aux + (size_t)r0 * M + cc;
                const float* x1 = x0 + (size_t)8 * M;
                v0 += x0[0]; v1 += x0[1]; v2 += x1[0]; v3 += x1[1];
                lmax = fmaxf(lmax, fmaxf(fmaxf(fabsf(v0), fabsf(v1)), fmaxf(fabsf(v2), fabsf(v3))));
            } else if (mode == 0) {
                v0 *= alpha; v1 *= alpha; v2 *= alpha; v3 *= alpha;
            } else if (mode == 2) {
                float b0 = aux[cc], b1 = aux[cc + 1];
                v0 = v0 * alpha + b0; v1 = v1 * alpha + b1;
                v2 = v2 * alpha + b0; v3 = v3 * alpha + b1;
            }
            p0[0] = v0; p0[1] = v1; p1[0] = v2; p1[1] = v3;
        }
    }
    if (mode == 1) {
        red[tid] = lmax; __syncthreads();
        for (int s = 256; s > 0; s >>= 1) {
            if (tid < s) red[tid] = fmaxf(red[tid], red[tid + s]);
            __syncthreads();
        }
        if (tid == 0) part[blockIdx.y * gridDim.x + blockIdx.x] = red[0];
    }
}

// ---------------- launch -----------------------------------------------------
extern "C" void kernel_launch(void* const* d_in, const int* in_sizes, int n_in,
                              void* d_out, int out_size) {
    const float* x  = (const float*)d_in[0];
    const float* mk = (const float*)d_in[1];
    const float* mv = (const float*)d_in[2];
    const float* Wk = (const float*)d_in[3];
    const float* bk = (const float*)d_in[4];
    // d_in[5], d_in[6] (Wv, bv) dead: _query_values never reaches output.
    const float* Wo = (const float*)d_in[7];
    const float* bo = (const float*)d_in[8];
    float* out = (float*)d_out;

    void *a0,*a1,*a2,*a3,*a4,*a6,*a7,*a8,*a9,*a10,*a11,*a12,*a13,*a14,*a15,*a16;
    cudaGetSymbolAddress(&a0, g_part);  cudaGetSymbolAddress(&a1, g_scal);
    cudaGetSymbolAddress(&a2, g_qxb);   cudaGetSymbolAddress(&a3, g_qwkT);
    cudaGetSymbolAddress(&a4, g_qwob);
    cudaGetSymbolAddress(&a6, g_ghi);   cudaGetSymbolAddress(&a7, g_glo);
    cudaGetSymbolAddress(&a8, g_mhiT);  cudaGetSymbolAddress(&a9, g_mloT);
    cudaGetSymbolAddress(&a10, g_c);    cudaGetSymbolAddress(&a11, g_sim);
    cudaGetSymbolAddress(&a12, g_ahi);  cudaGetSymbolAddress(&a13, g_alo);
    cudaGetSymbolAddress(&a14, g_h);    cudaGetSymbolAddress(&a15, g_mkhi);
    cudaGetSymbolAddress(&a16, g_mklo);
    float* part = (float*)a0;  float* scal = (float*)a1;
    bf16* qxb = (bf16*)a2;     bf16* qwkT = (bf16*)a3;
    bf16* qwob = (bf16*)a4;
    bf16* ghi = (bf16*)a6;     bf16* glo = (bf16*)a7;
    bf16* mhiT = (bf16*)a8;    bf16* mloT = (bf16*)a9;
    float* cvec = (float*)a10; float* sim = (float*)a11;
    bf16* ahi = (bf16*)a12;    bf16* alo = (bf16*)a13;
    float* h = (float*)a14;
    bf16* mkhi = (bf16*)a15;   bf16* mklo = (bf16*)a16;

    const size_t nx = (size_t)NROWS * EDIM;
    const size_t nw = (size_t)EDIM * EDIM;
    const size_t ng = (size_t)MSIZE * EDIM;
    const int SMEM_TC = 2 * 49152;   // 96 KB double-buffered
    cudaFuncSetAttribute(tc_gemm, cudaFuncAttributeMaxDynamicSharedMemorySize, SMEM_TC);

    // split mk -> hi/lo (exact to 2^-17)
    split2<<<(unsigned)((ng + 255) / 256), 256>>>(mk, mkhi, mklo, ng);
    // wsk
    abssum_part<<<512, 256>>>(Wk, nw / 4, part + 2048);
    finalize_mean<<<1, 256>>>(part + 2048, 512, scal + 2, (float)nw);
    // quantize+transpose Wk -> bf16 [i,d]
    tq_wkT<<<dim3(32, 32), dim3(32, 8)>>>(Wk, qwkT, scal);
    // bias fold vector
    cvec_k<<<MSIZE / 8, 256>>>(mk, bk, cvec);
    // G = (mkhi+mklo) @ qwkT^T  [2 passes], split epilogue -> ghi/glo
    tc_gemm<<<dim3(EDIM / 256, MSIZE / 128), 512, SMEM_TC>>>(
        mkhi, mklo, nullptr, qwkT, qwkT, nullptr, 2, EDIM, nullptr, nullptr,
        scal, nullptr, 3, EDIM, ghi, glo);
    // xmax, qx
    absmax_part<<<2048, 256>>>(x, nx / 4, part);
    finalize_max<<<1, 256>>>(part, 2048, scal + 0);
    quantize_act_bf16<<<(unsigned)(nx / 4 / 256), 256>>>(x, qxb, scal + 0, nx / 4);
    // wso, qWo
    abssum_part<<<512, 256>>>(Wo, nw / 4, part + 2560);
    finalize_mean<<<1, 256>>>(part + 2560, 512, scal + 3, (float)nw);
    quantize_w_bf16<<<(unsigned)(nw / 256), 256>>>(Wo, qwob, scal + 3, nw);
    // mv transpose+split
    transpose_split<<<dim3(EDIM / 32, MSIZE / 32), dim3(32, 8)>>>(mv, mhiT, mloT);
    // sim = alpha0 * qx @ (Ghi+Glo)^T  [2 passes]
    tc_gemm<<<dim3(MSIZE / 256, NROWS / 128), 512, SMEM_TC>>>(
        qxb, qxb, nullptr, ghi, glo, nullptr, 2, EDIM, sim, nullptr,
        scal, nullptr, 0, MSIZE, nullptr, nullptr);
    // softmax -> attn hi/lo
    softmax_split<<<NROWS, 256>>>(sim, cvec, ahi, alo);
    // h = x + ahi@mhi + alo@mhi + ahi@mlo  [3 passes] + fused absmax
    tc_gemm<<<dim3(EDIM / 256, NROWS / 128), 512, SMEM_TC>>>(
        ahi, alo, ahi, mhiT, mhiT, mloT, 3, MSIZE, h, x,
        scal, part, 1, EDIM, nullptr, nullptr);
    // hmax
    finalize_max<<<1, 256>>>(part, (EDIM / 256) * (NROWS / 128), scal + 1);
    // qh
    quantize_act_bf16<<<(unsigned)(nx / 4 / 256), 256>>>(h, qxb, scal + 1, nx / 4);
    // out = alpha2 * qh @ qWo^T + bo  [exact]
    tc_gemm<<<dim3(EDIM / 256, NROWS / 128), 512, SMEM_TC>>>(
        qxb, nullptr, nullptr, qwob, nullptr, nullptr, 1, EDIM, out, bo,
        scal, nullptr, 2, EDIM, nullptr, nullptr);
}

// round 11
// speedup vs baseline: 1.1130x; 1.1130x over previous
#include <cuda_runtime.h>
#include <cuda_bf16.h>
#include <cstddef>
#include <cstdint>

#define NROWS 32768
#define EDIM  1024
#define MSIZE 2048
typedef __nv_bfloat16 bf16;

// ---------------- scratch ----------------------------------------------------
__device__ float g_part[4096];
__device__ float g_scal[8];           // 0 xmax, 1 hmax, 2 wsk, 3 wso
__device__ bf16  g_qxb [(size_t)NROWS * EDIM];    // qx / qh as exact-int bf16
__device__ bf16  g_qwkT[(size_t)EDIM * EDIM];     // quantized Wk, transposed [i,d]
__device__ bf16  g_qwob[(size_t)EDIM * EDIM];     // quantized Wo [o,i]
__device__ bf16  g_mkhi[(size_t)MSIZE * EDIM];
__device__ bf16  g_mklo[(size_t)MSIZE * EDIM];
__device__ bf16  g_ghi [(size_t)MSIZE * EDIM];
__device__ bf16  g_glo [(size_t)MSIZE * EDIM];
__device__ bf16  g_mhiT[(size_t)EDIM * MSIZE];
__device__ bf16  g_mloT[(size_t)EDIM * MSIZE];
__device__ float g_c   [MSIZE];
__device__ float g_sim [(size_t)NROWS * MSIZE];
__device__ bf16  g_ahi [(size_t)NROWS * MSIZE];
__device__ bf16  g_alo [(size_t)NROWS * MSIZE];
__device__ float g_h   [(size_t)NROWS * EDIM];

// ---------------- helpers ----------------------------------------------------
__device__ __forceinline__ uint32_t smem_u32(const void* p) {
    uint32_t a;
    asm("{ .reg .u64 t; cvta.to.shared.u64 t, %1; cvt.u32.u64 %0, t; }" : "=r"(a) : "l"(p));
    return a;
}
// 128B-row swizzle: 16B unit g ^= (row & 7)
__device__ __forceinline__ uint32_t sw_addr(uint32_t base, int r, int g) {
    return base + r * 128 + ((g ^ (r & 7)) << 4);
}
__device__ __forceinline__ void cp16(uint32_t s, const void* g) {
    asm volatile("cp.async.cg.shared.global [%0], [%1], 16;" :: "r"(s), "l"(g));
}
#define CP_COMMIT() asm volatile("cp.async.commit_group;" ::: "memory")
#define CP_WAIT0()  asm volatile("cp.async.wait_group 0;" ::: "memory")
#define LDSM4(r0, r1, r2, r3, addr) \
    asm volatile("ldmatrix.sync.aligned.m8n8.x4.shared.b16 {%0,%1,%2,%3}, [%4];" \
                 : "=r"(r0), "=r"(r1), "=r"(r2), "=r"(r3) : "r"(addr))
#define MMA_BF16(c, a, b0r, b1r) \
    asm volatile("mma.sync.aligned.m16n8k16.row.col.f32.bf16.bf16.f32 " \
                 "{%0,%1,%2,%3}, {%4,%5,%6,%7}, {%8,%9}, {%0,%1,%2,%3};" \
                 : "+f"((c)[0]), "+f"((c)[1]), "+f"((c)[2]), "+f"((c)[3]) \
                 : "r"((a)[0]), "r"((a)[1]), "r"((a)[2]), "r"((a)[3]), "r"(b0r), "r"(b1r))

// ---------------- reductions -------------------------------------------------
__global__ void absmax_part(const float* __restrict__ x, size_t n4, float* __restrict__ part) {
    const float4* x4 = (const float4*)x;
    float m = 0.f;
    for (size_t i = (size_t)blockIdx.x * blockDim.x + threadIdx.x; i < n4;
         i += (size_t)gridDim.x * blockDim.x) {
        float4 v = x4[i];
        m = fmaxf(m, fmaxf(fmaxf(fabsf(v.x), fabsf(v.y)), fmaxf(fabsf(v.z), fabsf(v.w))));
    }
    __shared__ float red[256];
    red[threadIdx.x] = m; __syncthreads();
    for (int s = 128; s > 0; s >>= 1) {
        if (threadIdx.x < s) red[threadIdx.x] = fmaxf(red[threadIdx.x], red[threadIdx.x + s]);
        __syncthreads();
    }
    if (threadIdx.x == 0) part[blockIdx.x] = red[0];
}

__global__ void abssum_part(const float* __restrict__ x, size_t n4, float* __restrict__ part) {
    const float4* x4 = (const float4*)x;
    float s = 0.f;
    for (size_t i = (size_t)blockIdx.x * blockDim.x + threadIdx.x; i < n4;
         i += (size_t)gridDim.x * blockDim.x) {
        float4 v = x4[i];
        s += fabsf(v.x) + fabsf(v.y) + fabsf(v.z) + fabsf(v.w);
    }
    __shared__ float red[256];
    red[threadIdx.x] = s; __syncthreads();
    for (int st = 128; st > 0; st >>= 1) {
        if (threadIdx.x < st) red[threadIdx.x] += red[threadIdx.x + st];
        __syncthreads();
    }
    if (threadIdx.x == 0) part[blockIdx.x] = red[0];
}

__global__ void finalize_max(const float* __restrict__ part, int npart, float* __restrict__ out) {
    __shared__ float red[256];
    float m = 0.f;
    for (int i = threadIdx.x; i < npart; i += 256) m = fmaxf(m, part[i]);
    red[threadIdx.x] = m; __syncthreads();
    for (int s = 128; s > 0; s >>= 1) {
        if (threadIdx.x < s) red[threadIdx.x] = fmaxf(red[threadIdx.x], red[threadIdx.x + s]);
        __syncthreads();
    }
    if (threadIdx.x == 0) out[0] = red[0];
}

__global__ void finalize_mean(const float* __restrict__ part, int npart, float* __restrict__ out, float n) {
    __shared__ float red[256];
    float s = 0.f;
    for (int i = threadIdx.x; i < npart; i += 256) s += part[i];
    red[threadIdx.x] = s; __syncthreads();
    for (int st = 128; st > 0; st >>= 1) {
        if (threadIdx.x < st) red[threadIdx.x] += red[threadIdx.x + st];
        __syncthreads();
    }
    if (threadIdx.x == 0) out[0] = __fdiv_rn(red[0], n);
}

// ---------------- quantize / split / transpose -------------------------------
__global__ void quantize_act_bf16(const float* __restrict__ x, bf16* __restrict__ q,
                                  const float* __restrict__ amax, size_t n4) {
    size_t i = (size_t)blockIdx.x * blockDim.x + threadIdx.x;
    if (i >= n4) return;
    float iscale = __fdiv_rn(amax[0], 127.0f);
    float4 v = ((const float4*)x)[i];
    float r0 = fminf(fmaxf(rintf(__fdiv_rn(v.x, iscale)), -128.f), 127.f);
    float r1 = fminf(fmaxf(rintf(__fdiv_rn(v.y, iscale)), -128.f), 127.f);
    float r2 = fminf(fmaxf(rintf(__fdiv_rn(v.z, iscale)), -128.f), 127.f);
    float r3 = fminf(fmaxf(rintf(__fdiv_rn(v.w, iscale)), -128.f), 127.f);
    bf16* o = q + i * 4;
    o[0] = __float2bfloat16(r0); o[1] = __float2bfloat16(r1);
    o[2] = __float2bfloat16(r2); o[3] = __float2bfloat16(r3);
}

__global__ void quantize_w_bf16(const float* __restrict__ W, bf16* __restrict__ q,
                                const float* __restrict__ wscale, size_t n) {
    size_t i = (size_t)blockIdx.x * blockDim.x + threadIdx.x;
    if (i >= n) return;
    float thr = 0.5f * wscale[0];
    float v = W[i];
    float o = (fabsf(v) > thr) ? (v > 0.f ? 1.f : -1.f) : 0.f;
    q[i] = __float2bfloat16(o);
}

// quantize Wk to bf16 ternary, transposed: q[i,d] = quant(W[d,i])
__global__ void tq_wkT(const float* __restrict__ W, bf16* __restrict__ q,
                       const float* __restrict__ scal) {
    __shared__ float t[32][33];
    int bd = blockIdx.y * 32, bi = blockIdx.x * 32;
    for (int j = threadIdx.y; j < 32; j += 8)
        t[j][threadIdx.x] = W[(size_t)(bd + j) * EDIM + bi + threadIdx.x];
    __syncthreads();
    float thr = 0.5f * scal[2];
    for (int j = threadIdx.y; j < 32; j += 8) {
        float v = t[threadIdx.x][j];
        float o = (fabsf(v) > thr) ? (v > 0.f ? 1.f : -1.f) : 0.f;
        q[(size_t)(bi + j) * EDIM + bd + threadIdx.x] = __float2bfloat16(o);
    }
}

// fp32 -> (hi, lo) bf16 split
__global__ void split2(const float* __restrict__ X, bf16* __restrict__ hi,
                       bf16* __restrict__ lo, size_t n) {
    size_t i = (size_t)blockIdx.x * blockDim.x + threadIdx.x;
    if (i >= n) return;
    float v = X[i];
    bf16 h = __float2bfloat16(v);
    hi[i] = h;
    lo[i] = __float2bfloat16(v - __bfloat162float(h));
}

// mv [MSIZE, EDIM] -> transposed split [EDIM, MSIZE]
__global__ void transpose_split(const float* __restrict__ mv, bf16* __restrict__ hi,
                                bf16* __restrict__ lo) {
    __shared__ float t[32][33];
    int bx = blockIdx.x * 32, by = blockIdx.y * 32;   // bx: e, by: m
    for (int i = threadIdx.y; i < 32; i += 8)
        t[i][threadIdx.x] = mv[(size_t)(by + i) * EDIM + bx + threadIdx.x];
    __syncthreads();
    for (int i = threadIdx.y; i < 32; i += 8) {
        float v = t[threadIdx.x][i];
        bf16 h = __float2bfloat16(v);
        size_t o = (size_t)(bx + i) * MSIZE + by + threadIdx.x;
        hi[o] = h;
        lo[o] = __float2bfloat16(v - __bfloat162float(h));
    }
}

__global__ void cvec_k(const float* __restrict__ mk, const float* __restrict__ bk,
                       float* __restrict__ c) {
    int m = blockIdx.x * 8 + (threadIdx.x >> 5);
    int lane = threadIdx.x & 31;
    const float4* row = (const float4*)(mk + (size_t)m * EDIM);
    const float4* b4 = (const float4*)bk;
    float s = 0.f;
    for (int i = lane; i < EDIM / 4; i += 32) {
        float4 a = row[i], b = b4[i];
        s += a.x * b.x + a.y * b.y + a.z * b.z + a.w * b.w;
    }
    for (int o = 16; o > 0; o >>= 1) s += __shfl_xor_sync(0xffffffffu, s, o);
    if (lane == 0) c[m] = s;
}

// -------- row softmax (+ c[m]/32), emit 2-level bf16 attn --------------------
__global__ void softmax_split(const float* __restrict__ S, const float* __restrict__ c,
                              bf16* __restrict__ ahi, bf16* __restrict__ alo) {
    const size_t row = blockIdx.x;
    const float* p = S + row * (size_t)MSIZE;
    const int tid = threadIdx.x;
    float v[8];
#pragma unroll
    for (int i = 0; i < 8; i++) v[i] = p[tid + i * 256] + c[tid + i * 256] * 0.03125f;
    float m = v[0];
#pragma unroll
    for (int i = 1; i < 8; i++) m = fmaxf(m, v[i]);
    __shared__ float red[256];
    red[tid] = m; __syncthreads();
    for (int s = 128; s > 0; s >>= 1) {
        if (tid < s) red[tid] = fmaxf(red[tid], red[tid + s]);
        __syncthreads();
    }
    const float rowmax = red[0];
    __syncthreads();
    float sum = 0.f;
#pragma unroll
    for (int i = 0; i < 8; i++) { v[i] = expf(v[i] - rowmax); sum += v[i]; }
    red[tid] = sum; __syncthreads();
    for (int s = 128; s > 0; s >>= 1) {
        if (tid < s) red[tid] += red[tid + s];
        __syncthreads();
    }
    const float inv = __fdiv_rn(1.0f, red[0]);
#pragma unroll
    for (int i = 0; i < 8; i++) {
        float a = v[i] * inv;
        bf16 h = __float2bfloat16(a);
        size_t o = row * (size_t)MSIZE + tid + i * 256;
        ahi[o] = h;
        alo[o] = __float2bfloat16(a - __bfloat162float(h));
    }
}

// ======= bf16 mma.sync GEMM NT, 128x128 tile, term-fused single K-sweep ======
// D = sum over terms t in tmask of At[bm..,K] @ Bt[bn..,K]^T  (fp32 accum)
// term bit t: ai = t>>1 in {A0,A1}, bi = t&1 in {B0,B1}
// mode 0: C = D*alpha0 ; mode 1: C = D + aux, absmax->part ;
// mode 2: C = D*alpha2 + aux[col] ; mode 3: (Ohi,Olo) = split(D)
__global__ __launch_bounds__(256)
void tc_gemm(const bf16* A0, const bf16* A1, const bf16* B0, const bf16* B1,
             int nA, int nB, int tmask, int K,
             float* __restrict__ C, const float* __restrict__ aux,
             const float* __restrict__ scal, float* __restrict__ part,
             int mode, int M, bf16* __restrict__ Ohi, bf16* __restrict__ Olo) {
    extern __shared__ char dsm[];
    __shared__ float red[256];
    const int tid = threadIdx.x, l = tid & 31, w = tid >> 5;
    const int bm = blockIdx.y * 128, bn = blockIdx.x * 128;
    const int wm = (w & 1) * 64, wn = (w >> 1) * 32;
    const int kchunks = K >> 6;
    const int ntiles = nA + nB;
    const uint32_t stageBytes = (uint32_t)ntiles * 16384u;
    const uint32_t sbase = smem_u32(dsm);

    const bf16* tp[4]; int rbase[4];
    {
        int n = 0;
        tp[n] = A0; rbase[n] = bm; n++;
        if (nA > 1) { tp[n] = A1; rbase[n] = bm; n++; }
        tp[n] = B0; rbase[n] = bn; n++;
        if (nB > 1) { tp[n] = B1; rbase[n] = bn; n++; }
    }

    float acc[4][4][4];
#pragma unroll
    for (int i = 0; i < 4; i++)
#pragma unroll
        for (int j = 0; j < 4; j++)
#pragma unroll
            for (int k = 0; k < 4; k++) acc[i][j][k] = 0.f;

    const int lr = tid >> 3, lg = tid & 7;
    // prefetch chunk 0 -> stage 0
    for (int t = 0; t < ntiles; t++) {
        const bf16* gp = tp[t] + (size_t)(rbase[t] + lr) * K + lg * 8;
        uint32_t s = sbase + t * 16384u;
#pragma unroll
        for (int i = 0; i < 4; i++)
            cp16(sw_addr(s, lr + i * 32, lg), gp + (size_t)i * 32 * K);
    }
    CP_COMMIT();
    CP_WAIT0();
    __syncthreads();

    for (int ch = 0; ch < kchunks; ch++) {
        const uint32_t st = sbase + (uint32_t)(ch & 1) * stageBytes;
        if (ch + 1 < kchunks) {
            const uint32_t nst = sbase + (uint32_t)((ch + 1) & 1) * stageBytes;
            for (int t = 0; t < ntiles; t++) {
                const bf16* gp = tp[t] + (size_t)(rbase[t] + lr) * K + (ch + 1) * 64 + lg * 8;
                uint32_t s = nst + t * 16384u;
#pragma unroll
                for (int i = 0; i < 4; i++)
                    cp16(sw_addr(s, lr + i * 32, lg), gp + (size_t)i * 32 * K);
            }
            CP_COMMIT();
        }
        const int rA = wm + (l & 15);
        const int rB = wn + (l & 7) + ((l & 16) ? 8 : 0);
        for (int t = 0; t < 4; t++) {
            if (!((tmask >> t) & 1)) continue;
            const uint32_t sA = st + (uint32_t)(t >> 1) * 16384u;
            const uint32_t sB = st + (uint32_t)(nA + (t & 1)) * 16384u;
#pragma unroll
            for (int ks = 0; ks < 4; ks++) {
                uint32_t a[4][4], b[2][4];
                const int gA = ks * 2 + (l >> 4);
                const int gB = ks * 2 + ((l >> 3) & 1);
#pragma unroll
                for (int mt = 0; mt < 4; mt++)
                    LDSM4(a[mt][0], a[mt][1], a[mt][2], a[mt][3], sw_addr(sA, rA + mt * 16, gA));
#pragma unroll
                for (int bp = 0; bp < 2; bp++)
                    LDSM4(b[bp][0], b[bp][1], b[bp][2], b[bp][3], sw_addr(sB, rB + bp * 16, gB));
#pragma unroll
                for (int mt = 0; mt < 4; mt++)
#pragma unroll
                    for (int nt = 0; nt < 4; nt++)
                        MMA_BF16(acc[mt][nt], a[mt], b[nt >> 1][(nt & 1) * 2], b[nt >> 1][(nt & 1) * 2 + 1]);
            }
        }
        if (ch + 1 < kchunks) CP_WAIT0();
        __syncthreads();
    }

    float alpha = 1.f;
    if (mode == 0) alpha = 0.03125f * scal[2] * __fdiv_rn(scal[0], 127.0f);
    else if (mode == 2) alpha = scal[3] * __fdiv_rn(scal[1], 127.0f);
    float lmax = 0.f;
    const int rr = bm + wm + (l >> 2);
    const int cbs = bn + wn + (l & 3) * 2;
#pragma unroll
    for (int mt = 0; mt < 4; mt++) {
        int r0 = rr + mt * 16;
#pragma unroll
        for (int nt = 0; nt < 4; nt++) {
            int cc = cbs + nt * 8;
            float v0 = acc[mt][nt][0], v1 = acc[mt][nt][1];
            float v2 = acc[mt][nt][2], v3 = acc[mt][nt][3];
            if (mode == 3) {
                bf16 h0 = __float2bfloat16(v0), h1 = __float2bfloat16(v1);
                bf16 h2 = __float2bfloat16(v2), h3 = __float2bfloat16(v3);
                size_t o0 = (size_t)r0 * M + cc, o1 = (size_t)(r0 + 8) * M + cc;
                Ohi[o0] = h0; Ohi[o0 + 1] = h1; Ohi[o1] = h2; Ohi[o1 + 1] = h3;
                Olo[o0] = __float2bfloat16(v0 - __bfloat162float(h0));
                Olo[o0 + 1] = __float2bfloat16(v1 - __bfloat162float(h1));
                Olo[o1] = __float2bfloat16(v2 - __bfloat162float(h2));
                Olo[o1 + 1] = __float2bfloat16(v3 - __bfloat162float(h3));
                continue;
            }
            float* p0 = C + (size_t)r0 * M + cc;
            float* p1 = p0 + (size_t)8 * M;
            if (mode == 1) {
                const float* x0 = aux + (size_t)r0 * M + cc;
                const float* x1 = x0 + (size_t)8 * M;
                v0 += x0[0]; v1 += x0[1]; v2 += x1[0]; v3 += x1[1];
                lmax = fmaxf(lmax, fmaxf(fmaxf(fabsf(v0), fabsf(v1)), fmaxf(fabsf(v2), fabsf(v3))));
            } else if (mode == 0) {
                v0 *= alpha; v1 *= alpha; v2 *= alpha; v3 *= alpha;
            } else if (mode == 2) {
                float b0 = aux[cc], b1 = aux[cc + 1];
                v0 = v0 * alpha + b0; v1 = v1 * alpha + b1;
                v2 = v2 * alpha + b0; v3 = v3 * alpha + b1;
            }
            p0[0] = v0; p0[1] = v1; p1[0] = v2; p1[1] = v3;
        }
    }
    if (mode == 1) {
        red[tid] = lmax; __syncthreads();
        for (int s = 128; s > 0; s >>= 1) {
            if (tid < s) red[tid] = fmaxf(red[tid], red[tid + s]);
            __syncthreads();
        }
        if (tid == 0) part[blockIdx.y * gridDim.x + blockIdx.x] = red[0];
    }
}

// ---------------- launch -----------------------------------------------------
extern "C" void kernel_launch(void* const* d_in, const int* in_sizes, int n_in,
                              void* d_out, int out_size) {
    const float* x  = (const float*)d_in[0];
    const float* mk = (const float*)d_in[1];
    const float* mv = (const float*)d_in[2];
    const float* Wk = (const float*)d_in[3];
    const float* bk = (const float*)d_in[4];
    // d_in[5], d_in[6] (Wv, bv) dead: _query_values never reaches output.
    const float* Wo = (const float*)d_in[7];
    const float* bo = (const float*)d_in[8];
    float* out = (float*)d_out;

    void *a0,*a1,*a2,*a3,*a4,*a6,*a7,*a8,*a9,*a10,*a11,*a12,*a13,*a14,*a15,*a16;
    cudaGetSymbolAddress(&a0, g_part);  cudaGetSymbolAddress(&a1, g_scal);
    cudaGetSymbolAddress(&a2, g_qxb);   cudaGetSymbolAddress(&a3, g_qwkT);
    cudaGetSymbolAddress(&a4, g_qwob);
    cudaGetSymbolAddress(&a6, g_ghi);   cudaGetSymbolAddress(&a7, g_glo);
    cudaGetSymbolAddress(&a8, g_mhiT);  cudaGetSymbolAddress(&a9, g_mloT);
    cudaGetSymbolAddress(&a10, g_c);    cudaGetSymbolAddress(&a11, g_sim);
    cudaGetSymbolAddress(&a12, g_ahi);  cudaGetSymbolAddress(&a13, g_alo);
    cudaGetSymbolAddress(&a14, g_h);    cudaGetSymbolAddress(&a15, g_mkhi);
    cudaGetSymbolAddress(&a16, g_mklo);
    float* part = (float*)a0;  float* scal = (float*)a1;
    bf16* qxb = (bf16*)a2;     bf16* qwkT = (bf16*)a3;
    bf16* qwob = (bf16*)a4;
    bf16* ghi = (bf16*)a6;     bf16* glo = (bf16*)a7;
    bf16* mhiT = (bf16*)a8;    bf16* mloT = (bf16*)a9;
    float* cvec = (float*)a10; float* sim = (float*)a11;
    bf16* ahi = (bf16*)a12;    bf16* alo = (bf16*)a13;
    float* h = (float*)a14;
    bf16* mkhi = (bf16*)a15;   bf16* mklo = (bf16*)a16;

    const size_t nx = (size_t)NROWS * EDIM;
    const size_t nw = (size_t)EDIM * EDIM;
    const size_t ng = (size_t)MSIZE * EDIM;
    cudaFuncSetAttribute(tc_gemm, cudaFuncAttributeMaxDynamicSharedMemorySize, 131072);

    // split mk -> hi/lo (exact to 2^-17)
    split2<<<(unsigned)((ng + 255) / 256), 256>>>(mk, mkhi, mklo, ng);
    // wsk
    abssum_part<<<512, 256>>>(Wk, nw / 4, part + 2048);
    finalize_mean<<<1, 256>>>(part + 2048, 512, scal + 2, (float)nw);
    // quantize+transpose Wk -> bf16 [i,d]
    tq_wkT<<<dim3(32, 32), dim3(32, 8)>>>(Wk, qwkT, scal);
    // bias fold vector
    cvec_k<<<MSIZE / 8, 256>>>(mk, bk, cvec);
    // G = mkhi@qwkT^T + mklo@qwkT^T  [fused], split epilogue -> ghi/glo
    tc_gemm<<<dim3(EDIM / 128, MSIZE / 128), 256, 3 * 32768>>>(
        mkhi, mklo, qwkT, nullptr, 2, 1, 0b0101, EDIM,
        nullptr, nullptr, scal, nullptr, 3, EDIM, ghi, glo);
    // xmax, qx
    absmax_part<<<2048, 256>>>(x, nx / 4, part);
    finalize_max<<<1, 256>>>(part, 2048, scal + 0);
    quantize_act_bf16<<<(unsigned)(nx / 4 / 256), 256>>>(x, qxb, scal + 0, nx / 4);
    // wso, qWo
    abssum_part<<<512, 256>>>(Wo, nw / 4, part + 2560);
    finalize_mean<<<1, 256>>>(part + 2560, 512, scal + 3, (float)nw);
    quantize_w_bf16<<<(unsigned)(nw / 256), 256>>>(Wo, qwob, scal + 3, nw);
    // mv transpose+split
    transpose_split<<<dim3(EDIM / 32, MSIZE / 32), dim3(32, 8)>>>(mv, mhiT, mloT);
    // sim = alpha0 * (qx@Ghi^T + qx@Glo^T)  [fused]
    tc_gemm<<<dim3(MSIZE / 128, NROWS / 128), 256, 3 * 32768>>>(
        qxb, nullptr, ghi, glo, 1, 2, 0b0011, EDIM,
        sim, nullptr, scal, nullptr, 0, MSIZE, nullptr, nullptr);
    // softmax -> attn hi/lo
    softmax_split<<<NROWS, 256>>>(sim, cvec, ahi, alo);
    // h = x + ahi@mhi + ahi@mlo + alo@mhi  [fused 3-term] + block absmax
    tc_gemm<<<dim3(EDIM / 128, NROWS / 128), 256, 4 * 32768>>>(
        ahi, alo, mhiT, mloT, 2, 2, 0b0111, MSIZE,
        h, x, scal, part, 1, EDIM, nullptr, nullptr);
    // hmax
    finalize_max<<<1, 256>>>(part, (EDIM / 128) * (NROWS / 128), scal + 1);
    // qh
    quantize_act_bf16<<<(unsigned)(nx / 4 / 256), 256>>>(h, qxb, scal + 1, nx / 4);
    // out = alpha2 * qh @ qWo^T + bo  [exact]
    tc_gemm<<<dim3(EDIM / 128, NROWS / 128), 256, 2 * 32768>>>(
        qxb, nullptr, qwob, nullptr, 1, 1, 0b0001, EDIM,
        out, bo, scal, nullptr, 2, EDIM, nullptr, nullptr);
}

// round 12
// speedup vs baseline: 1.1134x; 1.0003x over previous
#include <cuda_runtime.h>
#include <cuda_bf16.h>
#include <cstddef>
#include <cstdint>

#define NROWS 32768
#define EDIM  1024
#define MSIZE 2048
typedef __nv_bfloat16 bf16;

// ---------------- scratch ----------------------------------------------------
__device__ float g_part[4096];
__device__ float g_scal[8];           // 0 xmax, 1 hmax, 2 wsk, 3 wso
__device__ bf16  g_qxb [(size_t)NROWS * EDIM];    // qx / qh as exact-int bf16
__device__ bf16  g_qwkT[(size_t)EDIM * EDIM];     // quantized Wk, transposed [i,d]
__device__ bf16  g_qwob[(size_t)EDIM * EDIM];     // quantized Wo [o,i]
__device__ bf16  g_mkhi[(size_t)MSIZE * EDIM];
__device__ bf16  g_mklo[(size_t)MSIZE * EDIM];
__device__ bf16  g_ghi [(size_t)MSIZE * EDIM];
__device__ bf16  g_glo [(size_t)MSIZE * EDIM];
__device__ bf16  g_mhiT[(size_t)EDIM * MSIZE];
__device__ bf16  g_mloT[(size_t)EDIM * MSIZE];
__device__ float g_c   [MSIZE];
__device__ float g_sim [(size_t)NROWS * MSIZE];
__device__ bf16  g_ahi [(size_t)NROWS * MSIZE];
__device__ bf16  g_alo [(size_t)NROWS * MSIZE];
__device__ float g_h   [(size_t)NROWS * EDIM];

// ---------------- helpers ----------------------------------------------------
__device__ __forceinline__ uint32_t smem_u32(const void* p) {
    uint32_t a;
    asm("{ .reg .u64 t; cvta.to.shared.u64 t, %1; cvt.u32.u64 %0, t; }" : "=r"(a) : "l"(p));
    return a;
}
// 128B-row swizzle: 16B unit g ^= (row & 7)
__device__ __forceinline__ uint32_t sw_addr(uint32_t base, int r, int g) {
    return base + r * 128 + ((g ^ (r & 7)) << 4);
}
__device__ __forceinline__ void cp16(uint32_t s, const void* g) {
    asm volatile("cp.async.cg.shared.global [%0], [%1], 16;" :: "r"(s), "l"(g));
}
#define CP_COMMIT() asm volatile("cp.async.commit_group;" ::: "memory")
#define CP_WAIT0()  asm volatile("cp.async.wait_group 0;" ::: "memory")
#define LDSM4(r0, r1, r2, r3, addr) \
    asm volatile("ldmatrix.sync.aligned.m8n8.x4.shared.b16 {%0,%1,%2,%3}, [%4];" \
                 : "=r"(r0), "=r"(r1), "=r"(r2), "=r"(r3) : "r"(addr))
#define MMA_BF16(c, a, b0r, b1r) \
    asm volatile("mma.sync.aligned.m16n8k16.row.col.f32.bf16.bf16.f32 " \
                 "{%0,%1,%2,%3}, {%4,%5,%6,%7}, {%8,%9}, {%0,%1,%2,%3};" \
                 : "+f"((c)[0]), "+f"((c)[1]), "+f"((c)[2]), "+f"((c)[3]) \
                 : "r"((a)[0]), "r"((a)[1]), "r"((a)[2]), "r"((a)[3]), "r"(b0r), "r"(b1r))

// ---------------- fused prologue ---------------------------------------------
// blocks [0,512): Wk abssum -> part[2048+]; [512,1024): Wo abssum -> part[2560+]
// blocks [1024, 1024+8192): mk elementwise split -> mkhi/mklo
__global__ void prep_all(const float* __restrict__ mk, const float* __restrict__ Wk,
                         const float* __restrict__ Wo,
                         bf16* __restrict__ mkhi, bf16* __restrict__ mklo,
                         float* __restrict__ part) {
    const int b = blockIdx.x, tid = threadIdx.x;
    if (b < 1024) {
        const float4* w4 = (const float4*)(b < 512 ? Wk : Wo);
        const int bb = (b < 512) ? b : b - 512;
        const size_t n4 = (size_t)EDIM * EDIM / 4;
        float s = 0.f;
        for (size_t i = (size_t)bb * 256 + tid; i < n4; i += (size_t)512 * 256) {
            float4 v = w4[i];
            s += fabsf(v.x) + fabsf(v.y) + fabsf(v.z) + fabsf(v.w);
        }
        __shared__ float red[256];
        red[tid] = s; __syncthreads();
        for (int st = 128; st > 0; st >>= 1) {
            if (tid < st) red[tid] += red[tid + st];
            __syncthreads();
        }
        if (tid == 0) part[(b < 512 ? 2048 : 2560) + bb] = red[0];
    } else {
        size_t i = (size_t)(b - 1024) * 256 + tid;
        if (i < (size_t)MSIZE * EDIM) {
            float v = mk[i];
            bf16 h = __float2bfloat16(v);
            mkhi[i] = h;
            mklo[i] = __float2bfloat16(v - __bfloat162float(h));
        }
    }
}

// both weight-scale means in one block
__global__ void finalize2(const float* __restrict__ part, float* __restrict__ scal) {
    __shared__ float red[256];
    const int tid = threadIdx.x;
    const float n = (float)((size_t)EDIM * EDIM);
    float s = 0.f;
    for (int i = tid; i < 512; i += 256) s += part[2048 + i];
    red[tid] = s; __syncthreads();
    for (int st = 128; st > 0; st >>= 1) {
        if (tid < st) red[tid] += red[tid + st];
        __syncthreads();
    }
    if (tid == 0) scal[2] = __fdiv_rn(red[0], n);
    __syncthreads();
    float s2 = 0.f;
    for (int i = tid; i < 512; i += 256) s2 += part[2560 + i];
    red[tid] = s2; __syncthreads();
    for (int st = 128; st > 0; st >>= 1) {
        if (tid < st) red[tid] += red[tid + st];
        __syncthreads();
    }
    if (tid == 0) scal[3] = __fdiv_rn(red[0], n);
}

// ---------------- reductions -------------------------------------------------
__global__ void absmax_part(const float* __restrict__ x, size_t n4, float* __restrict__ part) {
    const float4* x4 = (const float4*)x;
    float m = 0.f;
    for (size_t i = (size_t)blockIdx.x * blockDim.x + threadIdx.x; i < n4;
         i += (size_t)gridDim.x * blockDim.x) {
        float4 v = x4[i];
        m = fmaxf(m, fmaxf(fmaxf(fabsf(v.x), fabsf(v.y)), fmaxf(fabsf(v.z), fabsf(v.w))));
    }
    __shared__ float red[256];
    red[threadIdx.x] = m; __syncthreads();
    for (int s = 128; s > 0; s >>= 1) {
        if (threadIdx.x < s) red[threadIdx.x] = fmaxf(red[threadIdx.x], red[threadIdx.x + s]);
        __syncthreads();
    }
    if (threadIdx.x == 0) part[blockIdx.x] = red[0];
}

__global__ void finalize_max(const float* __restrict__ part, int npart, float* __restrict__ out) {
    __shared__ float red[256];
    float m = 0.f;
    for (int i = threadIdx.x; i < npart; i += 256) m = fmaxf(m, part[i]);
    red[threadIdx.x] = m; __syncthreads();
    for (int s = 128; s > 0; s >>= 1) {
        if (threadIdx.x < s) red[threadIdx.x] = fmaxf(red[threadIdx.x], red[threadIdx.x + s]);
        __syncthreads();
    }
    if (threadIdx.x == 0) out[0] = red[0];
}

// ---------------- quantize / split / transpose -------------------------------
__global__ void quantize_act_bf16(const float* __restrict__ x, bf16* __restrict__ q,
                                  const float* __restrict__ amax, size_t n4) {
    size_t i = (size_t)blockIdx.x * blockDim.x + threadIdx.x;
    if (i >= n4) return;
    float iscale = __fdiv_rn(amax[0], 127.0f);
    float4 v = ((const float4*)x)[i];
    float r0 = fminf(fmaxf(rintf(__fdiv_rn(v.x, iscale)), -128.f), 127.f);
    float r1 = fminf(fmaxf(rintf(__fdiv_rn(v.y, iscale)), -128.f), 127.f);
    float r2 = fminf(fmaxf(rintf(__fdiv_rn(v.z, iscale)), -128.f), 127.f);
    float r3 = fminf(fmaxf(rintf(__fdiv_rn(v.w, iscale)), -128.f), 127.f);
    bf16* o = q + i * 4;
    o[0] = __float2bfloat16(r0); o[1] = __float2bfloat16(r1);
    o[2] = __float2bfloat16(r2); o[3] = __float2bfloat16(r3);
}

__global__ void quantize_w_bf16(const float* __restrict__ W, bf16* __restrict__ q,
                                const float* __restrict__ wscale, size_t n) {
    size_t i = (size_t)blockIdx.x * blockDim.x + threadIdx.x;
    if (i >= n) return;
    float thr = 0.5f * wscale[0];
    float v = W[i];
    float o = (fabsf(v) > thr) ? (v > 0.f ? 1.f : -1.f) : 0.f;
    q[i] = __float2bfloat16(o);
}

// quantize Wk to bf16 ternary, transposed: q[i,d] = quant(W[d,i])
__global__ void tq_wkT(const float* __restrict__ W, bf16* __restrict__ q,
                       const float* __restrict__ scal) {
    __shared__ float t[32][33];
    int bd = blockIdx.y * 32, bi = blockIdx.x * 32;
    for (int j = threadIdx.y; j < 32; j += 8)
        t[j][threadIdx.x] = W[(size_t)(bd + j) * EDIM + bi + threadIdx.x];
    __syncthreads();
    float thr = 0.5f * scal[2];
    for (int j = threadIdx.y; j < 32; j += 8) {
        float v = t[threadIdx.x][j];
        float o = (fabsf(v) > thr) ? (v > 0.f ? 1.f : -1.f) : 0.f;
        q[(size_t)(bi + j) * EDIM + bd + threadIdx.x] = __float2bfloat16(o);
    }
}

// mv [MSIZE, EDIM] -> transposed split [EDIM, MSIZE]
__global__ void transpose_split(const float* __restrict__ mv, bf16* __restrict__ hi,
                                bf16* __restrict__ lo) {
    __shared__ float t[32][33];
    int bx = blockIdx.x * 32, by = blockIdx.y * 32;   // bx: e, by: m
    for (int i = threadIdx.y; i < 32; i += 8)
        t[i][threadIdx.x] = mv[(size_t)(by + i) * EDIM + bx + threadIdx.x];
    __syncthreads();
    for (int i = threadIdx.y; i < 32; i += 8) {
        float v = t[threadIdx.x][i];
        bf16 h = __float2bfloat16(v);
        size_t o = (size_t)(bx + i) * MSIZE + by + threadIdx.x;
        hi[o] = h;
        lo[o] = __float2bfloat16(v - __bfloat162float(h));
    }
}

__global__ void cvec_k(const float* __restrict__ mk, const float* __restrict__ bk,
                       float* __restrict__ c) {
    int m = blockIdx.x * 8 + (threadIdx.x >> 5);
    int lane = threadIdx.x & 31;
    const float4* row = (const float4*)(mk + (size_t)m * EDIM);
    const float4* b4 = (const float4*)bk;
    float s = 0.f;
    for (int i = lane; i < EDIM / 4; i += 32) {
        float4 a = row[i], b = b4[i];
        s += a.x * b.x + a.y * b.y + a.z * b.z + a.w * b.w;
    }
    for (int o = 16; o > 0; o >>= 1) s += __shfl_xor_sync(0xffffffffu, s, o);
    if (lane == 0) c[m] = s;
}

// -------- row softmax (+ c[m]/32), emit 2-level bf16 attn --------------------
__global__ void softmax_split(const float* __restrict__ S, const float* __restrict__ c,
                              bf16* __restrict__ ahi, bf16* __restrict__ alo) {
    const size_t row = blockIdx.x;
    const float* p = S + row * (size_t)MSIZE;
    const int tid = threadIdx.x;
    float v[8];
#pragma unroll
    for (int i = 0; i < 8; i++) v[i] = p[tid + i * 256] + c[tid + i * 256] * 0.03125f;
    float m = v[0];
#pragma unroll
    for (int i = 1; i < 8; i++) m = fmaxf(m, v[i]);
    __shared__ float red[256];
    red[tid] = m; __syncthreads();
    for (int s = 128; s > 0; s >>= 1) {
        if (tid < s) red[tid] = fmaxf(red[tid], red[tid + s]);
        __syncthreads();
    }
    const float rowmax = red[0];
    __syncthreads();
    float sum = 0.f;
#pragma unroll
    for (int i = 0; i < 8; i++) { v[i] = expf(v[i] - rowmax); sum += v[i]; }
    red[tid] = sum; __syncthreads();
    for (int s = 128; s > 0; s >>= 1) {
        if (tid < s) red[tid] += red[tid + s];
        __syncthreads();
    }
    const float inv = __fdiv_rn(1.0f, red[0]);
#pragma unroll
    for (int i = 0; i < 8; i++) {
        float a = v[i] * inv;
        bf16 h = __float2bfloat16(a);
        size_t o = row * (size_t)MSIZE + tid + i * 256;
        ahi[o] = h;
        alo[o] = __float2bfloat16(a - __bfloat162float(h));
    }
}

// ======= bf16 mma.sync GEMM NT, 128x128 tile, term-fused single K-sweep ======
// D = sum over terms t in tmask of At[bm..,K] @ Bt[bn..,K]^T  (fp32 accum)
// term bit t: ai = t>>1 in {A0,A1}, bi = t&1 in {B0,B1}
// mode 0: C = D*alpha0 ; mode 1: C = D + aux, absmax->part if part!=null ;
// mode 2: C = D*alpha2 + aux[col] ; mode 3: (Ohi,Olo) = split(D)
__global__ __launch_bounds__(256)
void tc_gemm(const bf16* A0, const bf16* A1, const bf16* B0, const bf16* B1,
             int nA, int nB, int tmask, int K,
             float* __restrict__ C, const float* __restrict__ aux,
             const float* __restrict__ scal, float* __restrict__ part,
             int mode, int M, bf16* __restrict__ Ohi, bf16* __restrict__ Olo) {
    extern __shared__ char dsm[];
    __shared__ float red[256];
    const int tid = threadIdx.x, l = tid & 31, w = tid >> 5;
    const int bm = blockIdx.y * 128, bn = blockIdx.x * 128;
    const int wm = (w & 1) * 64, wn = (w >> 1) * 32;
    const int kchunks = K >> 6;
    const int ntiles = nA + nB;
    const uint32_t stageBytes = (uint32_t)ntiles * 16384u;
    const uint32_t sbase = smem_u32(dsm);

    const bf16* tp[4]; int rbase[4];
    {
        int n = 0;
        tp[n] = A0; rbase[n] = bm; n++;
        if (nA > 1) { tp[n] = A1; rbase[n] = bm; n++; }
        tp[n] = B0; rbase[n] = bn; n++;
        if (nB > 1) { tp[n] = B1; rbase[n] = bn; n++; }
    }

    float acc[4][4][4];
#pragma unroll
    for (int i = 0; i < 4; i++)
#pragma unroll
        for (int j = 0; j < 4; j++)
#pragma unroll
            for (int k = 0; k < 4; k++) acc[i][j][k] = 0.f;

    const int lr = tid >> 3, lg = tid & 7;
    // prefetch chunk 0 -> stage 0
    for (int t = 0; t < ntiles; t++) {
        const bf16* gp = tp[t] + (size_t)(rbase[t] + lr) * K + lg * 8;
        uint32_t s = sbase + t * 16384u;
#pragma unroll
        for (int i = 0; i < 4; i++)
            cp16(sw_addr(s, lr + i * 32, lg), gp + (size_t)i * 32 * K);
    }
    CP_COMMIT();
    CP_WAIT0();
    __syncthreads();

    for (int ch = 0; ch < kchunks; ch++) {
        const uint32_t st = sbase + (uint32_t)(ch & 1) * stageBytes;
        if (ch + 1 < kchunks) {
            const uint32_t nst = sbase + (uint32_t)((ch + 1) & 1) * stageBytes;
            for (int t = 0; t < ntiles; t++) {
                const bf16* gp = tp[t] + (size_t)(rbase[t] + lr) * K + (ch + 1) * 64 + lg * 8;
                uint32_t s = nst + t * 16384u;
#pragma unroll
                for (int i = 0; i < 4; i++)
                    cp16(sw_addr(s, lr + i * 32, lg), gp + (size_t)i * 32 * K);
            }
            CP_COMMIT();
        }
        const int rA = wm + (l & 15);
        const int rB = wn + (l & 7) + ((l & 16) ? 8 : 0);
        for (int t = 0; t < 4; t++) {
            if (!((tmask >> t) & 1)) continue;
            const uint32_t sA = st + (uint32_t)(t >> 1) * 16384u;
            const uint32_t sB = st + (uint32_t)(nA + (t & 1)) * 16384u;
#pragma unroll
            for (int ks = 0; ks < 4; ks++) {
                uint32_t a[4][4], b[2][4];
                const int gA = ks * 2 + (l >> 4);
                const int gB = ks * 2 + ((l >> 3) & 1);
#pragma unroll
                for (int mt = 0; mt < 4; mt++)
                    LDSM4(a[mt][0], a[mt][1], a[mt][2], a[mt][3], sw_addr(sA, rA + mt * 16, gA));
#pragma unroll
                for (int bp = 0; bp < 2; bp++)
                    LDSM4(b[bp][0], b[bp][1], b[bp][2], b[bp][3], sw_addr(sB, rB + bp * 16, gB));
#pragma unroll
                for (int mt = 0; mt < 4; mt++)
#pragma unroll
                    for (int nt = 0; nt < 4; nt++)
                        MMA_BF16(acc[mt][nt], a[mt], b[nt >> 1][(nt & 1) * 2], b[nt >> 1][(nt & 1) * 2 + 1]);
            }
        }
        if (ch + 1 < kchunks) CP_WAIT0();
        __syncthreads();
    }

    float alpha = 1.f;
    if (mode == 0) alpha = 0.03125f * scal[2] * __fdiv_rn(scal[0], 127.0f);
    else if (mode == 2) alpha = scal[3] * __fdiv_rn(scal[1], 127.0f);
    float lmax = 0.f;
    const int rr = bm + wm + (l >> 2);
    const int cbs = bn + wn + (l & 3) * 2;
#pragma unroll
    for (int mt = 0; mt < 4; mt++) {
        int r0 = rr + mt * 16;
#pragma unroll
        for (int nt = 0; nt < 4; nt++) {
            int cc = cbs + nt * 8;
            float v0 = acc[mt][nt][0], v1 = acc[mt][nt][1];
            float v2 = acc[mt][nt][2], v3 = acc[mt][nt][3];
            if (mode == 3) {
                bf16 h0 = __float2bfloat16(v0), h1 = __float2bfloat16(v1);
                bf16 h2 = __float2bfloat16(v2), h3 = __float2bfloat16(v3);
                size_t o0 = (size_t)r0 * M + cc, o1 = (size_t)(r0 + 8) * M + cc;
                Ohi[o0] = h0; Ohi[o0 + 1] = h1; Ohi[o1] = h2; Ohi[o1 + 1] = h3;
                Olo[o0] = __float2bfloat16(v0 - __bfloat162float(h0));
                Olo[o0 + 1] = __float2bfloat16(v1 - __bfloat162float(h1));
                Olo[o1] = __float2bfloat16(v2 - __bfloat162float(h2));
                Olo[o1 + 1] = __float2bfloat16(v3 - __bfloat162float(h3));
                continue;
            }
            float* p0 = C + (size_t)r0 * M + cc;
            float* p1 = p0 + (size_t)8 * M;
            if (mode == 1) {
                const float* x0 = aux + (size_t)r0 * M + cc;
                const float* x1 = x0 + (size_t)8 * M;
                v0 += x0[0]; v1 += x0[1]; v2 += x1[0]; v3 += x1[1];
                lmax = fmaxf(lmax, fmaxf(fmaxf(fabsf(v0), fabsf(v1)), fmaxf(fabsf(v2), fabsf(v3))));
            } else if (mode == 0) {
                v0 *= alpha; v1 *= alpha; v2 *= alpha; v3 *= alpha;
            } else if (mode == 2) {
                float b0 = aux[cc], b1 = aux[cc + 1];
                v0 = v0 * alpha + b0; v1 = v1 * alpha + b1;
                v2 = v2 * alpha + b0; v3 = v3 * alpha + b1;
            }
            p0[0] = v0; p0[1] = v1; p1[0] = v2; p1[1] = v3;
        }
    }
    if (mode == 1 && part) {
        red[tid] = lmax; __syncthreads();
        for (int s = 128; s > 0; s >>= 1) {
            if (tid < s) red[tid] = fmaxf(red[tid], red[tid + s]);
            __syncthreads();
        }
        if (tid == 0) part[blockIdx.y * gridDim.x + blockIdx.x] = red[0];
    }
}

// ---------------- launch -----------------------------------------------------
extern "C" void kernel_launch(void* const* d_in, const int* in_sizes, int n_in,
                              void* d_out, int out_size) {
    const float* x  = (const float*)d_in[0];
    const float* mk = (const float*)d_in[1];
    const float* mv = (const float*)d_in[2];
    const float* Wk = (const float*)d_in[3];
    const float* bk = (const float*)d_in[4];
    // d_in[5], d_in[6] (Wv, bv) dead: _query_values never reaches output.
    const float* Wo = (const float*)d_in[7];
    const float* bo = (const float*)d_in[8];
    float* out = (float*)d_out;

    void *a0,*a1,*a2,*a3,*a4,*a6,*a7,*a8,*a9,*a10,*a11,*a12,*a13,*a14,*a15,*a16;
    cudaGetSymbolAddress(&a0, g_part);  cudaGetSymbolAddress(&a1, g_scal);
    cudaGetSymbolAddress(&a2, g_qxb);   cudaGetSymbolAddress(&a3, g_qwkT);
    cudaGetSymbolAddress(&a4, g_qwob);
    cudaGetSymbolAddress(&a6, g_ghi);   cudaGetSymbolAddress(&a7, g_glo);
    cudaGetSymbolAddress(&a8, g_mhiT);  cudaGetSymbolAddress(&a9, g_mloT);
    cudaGetSymbolAddress(&a10, g_c);    cudaGetSymbolAddress(&a11, g_sim);
    cudaGetSymbolAddress(&a12, g_ahi);  cudaGetSymbolAddress(&a13, g_alo);
    cudaGetSymbolAddress(&a14, g_h);    cudaGetSymbolAddress(&a15, g_mkhi);
    cudaGetSymbolAddress(&a16, g_mklo);
    float* part = (float*)a0;  float* scal = (float*)a1;
    bf16* qxb = (bf16*)a2;     bf16* qwkT = (bf16*)a3;
    bf16* qwob = (bf16*)a4;
    bf16* ghi = (bf16*)a6;     bf16* glo = (bf16*)a7;
    bf16* mhiT = (bf16*)a8;    bf16* mloT = (bf16*)a9;
    float* cvec = (float*)a10; float* sim = (float*)a11;
    bf16* ahi = (bf16*)a12;    bf16* alo = (bf16*)a13;
    float* h = (float*)a14;
    bf16* mkhi = (bf16*)a15;   bf16* mklo = (bf16*)a16;

    const size_t nx = (size_t)NROWS * EDIM;
    const size_t nw = (size_t)EDIM * EDIM;
    const size_t ng = (size_t)MSIZE * EDIM;
    cudaFuncSetAttribute(tc_gemm, cudaFuncAttributeMaxDynamicSharedMemorySize, 131072);

    // 0: fused prologue (Wk/Wo abssum partials + mk split)
    prep_all<<<1024 + (unsigned)((ng + 255) / 256), 256>>>(mk, Wk, Wo, mkhi, mklo, part);
    // 1: both weight scales
    finalize2<<<1, 256>>>(part, scal);
    // 2: quantize+transpose Wk -> bf16 [i,d]
    tq_wkT<<<dim3(32, 32), dim3(32, 8)>>>(Wk, qwkT, scal);
    // 3: G = mkhi@qwkT^T + mklo@qwkT^T, split epilogue -> ghi/glo  <- ncu slot
    tc_gemm<<<dim3(EDIM / 128, MSIZE / 128), 256, 3 * 32768>>>(
        mkhi, mklo, qwkT, nullptr, 2, 1, 0b0101, EDIM,
        nullptr, nullptr, scal, nullptr, 3, EDIM, ghi, glo);
    // 4-6: xmax, qx
    absmax_part<<<2048, 256>>>(x, nx / 4, part);
    finalize_max<<<1, 256>>>(part, 2048, scal + 0);
    quantize_act_bf16<<<(unsigned)(nx / 4 / 256), 256>>>(x, qxb, scal + 0, nx / 4);
    // 7: qWo
    quantize_w_bf16<<<(unsigned)(nw / 256), 256>>>(Wo, qwob, scal + 3, nw);
    // 8: mv transpose+split
    transpose_split<<<dim3(EDIM / 32, MSIZE / 32), dim3(32, 8)>>>(mv, mhiT, mloT);
    // 9: bias fold vector
    cvec_k<<<MSIZE / 8, 256>>>(mk, bk, cvec);
    // 10: sim = alpha0 * (qx@Ghi^T + qx@Glo^T)  [fused]
    tc_gemm<<<dim3(MSIZE / 128, NROWS / 128), 256, 3 * 32768>>>(
        qxb, nullptr, ghi, glo, 1, 2, 0b0011, EDIM,
        sim, nullptr, scal, nullptr, 0, MSIZE, nullptr, nullptr);
    // 11: softmax -> attn hi/lo
    softmax_split<<<NROWS, 256>>>(sim, cvec, ahi, alo);
    // 12: h = x + (ahi+alo)@mhi  [3 tiles, 96KB -> 2 CTA/SM]
    tc_gemm<<<dim3(EDIM / 128, NROWS / 128), 256, 3 * 32768>>>(
        ahi, alo, mhiT, nullptr, 2, 1, 0b0101, MSIZE,
        h, x, scal, nullptr, 1, EDIM, nullptr, nullptr);
    // 13: h += ahi@mlo  [2 tiles, 64KB -> 3 CTA/SM] + fused absmax
    tc_gemm<<<dim3(EDIM / 128, NROWS / 128), 256, 2 * 32768>>>(
        ahi, nullptr, mloT, nullptr, 1, 1, 0b0001, MSIZE,
        h, h, scal, part, 1, EDIM, nullptr, nullptr);
    // 14: hmax
    finalize_max<<<1, 256>>>(part, (EDIM / 128) * (NROWS / 128), scal + 1);
    // 15: qh
    quantize_act_bf16<<<(unsigned)(nx / 4 / 256), 256>>>(h, qxb, scal + 1, nx / 4);
    // 16: out = alpha2 * qh @ qWo^T + bo  [exact]
    tc_gemm<<<dim3(EDIM / 128, NROWS / 128), 256, 2 * 32768>>>(
        qxb, nullptr, qwob, nullptr, 1, 1, 0b0001, EDIM,
        out, bo, scal, nullptr, 2, EDIM, nullptr, nullptr);
}